// round 4
// baseline (speedup 1.0000x reference)
#include <cuda_runtime.h>
#include <math.h>

#define BB 64
#define SS 512
#define HH 768
#define LL 9
#define NTOK (BB*SS)
#define TPW 4              // tokens per warp
#define WPB 8              // warps per block (256 threads)
#define TOKPB (TPW*WPB)    // 32 tokens per block (one row spans 16 blocks)
#define WPAD 10            // W row stride in floats: LL=9 + 1 zero pad; LDS.64 conflict-free
#define NLP 5              // label pairs (9 labels + 1 pad)

typedef unsigned long long u64;

__device__ __forceinline__ u64 dup2(float v) {
    u64 r; asm("mov.b64 %0, {%1, %1};" : "=l"(r) : "f"(v)); return r;
}
__device__ __forceinline__ void unpack2(u64 v, float &lo, float &hi) {
    asm("mov.b64 {%0, %1}, %2;" : "=f"(lo), "=f"(hi) : "l"(v));
}
__device__ __forceinline__ void ffma2(u64 &d, u64 a, u64 b) {
    asm("fma.rn.f32x2 %0, %1, %2, %0;" : "+l"(d) : "l"(a), "l"(b));
}
__device__ __forceinline__ u64 fadd2(u64 a, u64 b) {
    u64 r; asm("add.rn.f32x2 %0, %1, %2;" : "=l"(r) : "l"(a), "l"(b)); return r;
}

// ---------------------------------------------------------------------------
// Single fused kernel:
//   1. per-block re-scan of this row's valid_mask -> slot code per token
//      (valid -> compacted slot, invalid -> tail slot; bijection over [0,512))
//   2. tall-skinny GEMM [4 tok/warp, 768] @ [768, 9] with f32x2 FMAs packed
//      across LABEL pairs (W pairs come straight from LDS.64, no dup packs)
//   3. bias + softmax + scatter (invalid tokens write softmax(bias))
// ---------------------------------------------------------------------------
__global__ __launch_bounds__(256, 3) void bertner_kernel(
    const float* __restrict__ X, const int* __restrict__ mask,
    const float* __restrict__ W, const float* __restrict__ bias,
    float* __restrict__ out) {

    __shared__ float shW[HH * WPAD];       // 30720 B
    __shared__ int   sh_slot[TOKPB];
    __shared__ int   sh_wsum[WPB];

    int tid  = threadIdx.x;
    int lane = tid & 31;
    int wid  = tid >> 5;

    // ---- cooperative W load into padded smem (pad column = 0) ----
    for (int idx = tid; idx < HH * LL; idx += 256) {
        int k = idx / LL;
        int j = idx - k * LL;
        shW[k * WPAD + j] = W[idx];
    }
    for (int k = tid; k < HH; k += 256) shW[k * WPAD + LL] = 0.f;

    // ---- per-row compaction scan (block redundantly scans its whole row) ----
    int tokblk = blockIdx.x * TOKPB;
    int row    = tokblk >> 9;          // / SS
    int r0     = tokblk & (SS - 1);    // row-local index of this block's first token

    int2 m2 = ((const int2*)(mask + row * SS))[tid];   // tokens 2*tid, 2*tid+1
    int msum = m2.x + m2.y;
    int v = msum;
    #pragma unroll
    for (int o = 1; o < 32; o <<= 1) {
        int n = __shfl_up_sync(0xffffffffu, v, o);
        if (lane >= o) v += n;
    }
    if (lane == 31) sh_wsum[wid] = v;
    __syncthreads();

    int wpre = 0, total = 0;
    #pragma unroll
    for (int w = 0; w < WPB; w++) {
        int s = sh_wsum[w];
        if (w < wid) wpre += s;
        total += s;
    }
    int run = wpre + v - msum;         // exclusive valid-prefix before token 2*tid

    int mm[2] = {m2.x, m2.y};
    #pragma unroll
    for (int c = 0; c < 2; c++) {
        int sc = 2 * tid + c;
        int code;
        if (mm[c]) { code = run; run++; }
        else       { code = ~(total + sc - run); }   // tail slot, encoded negative
        if (sc >= r0 && sc < r0 + TOKPB) sh_slot[sc - r0] = code;
    }
    __syncthreads();   // covers shW + sh_slot

    // ---- main GEMM: warp handles 4 tokens, lane owns k = lane + 32*i ----
    int tok0 = tokblk + wid * TPW;
    const float* xb = X + (size_t)tok0 * HH;

    u64 acc[TPW][NLP];
    #pragma unroll
    for (int t = 0; t < TPW; t++)
        #pragma unroll
        for (int p = 0; p < NLP; p++) acc[t][p] = 0ull;

    #pragma unroll 2
    for (int i = 0; i < HH / 32; i++) {       // 24 iterations
        int k = i * 32 + lane;
        const u64* wrow = (const u64*)(shW + k * WPAD);   // 8B-aligned (40k bytes)
        u64 w[NLP];
        #pragma unroll
        for (int p = 0; p < NLP; p++) w[p] = wrow[p];     // LDS.64, conflict-free

        float xv[TPW];
        #pragma unroll
        for (int t = 0; t < TPW; t++) xv[t] = xb[t * HH + k];
        u64 xp[TPW];
        #pragma unroll
        for (int t = 0; t < TPW; t++) xp[t] = dup2(xv[t]);

        #pragma unroll
        for (int t = 0; t < TPW; t++)
            #pragma unroll
            for (int p = 0; p < NLP; p++) ffma2(acc[t][p], xp[t], w[p]);
    }

    // ---- packed butterfly reduction: every lane ends with full sums ----
    #pragma unroll
    for (int t = 0; t < TPW; t++)
        #pragma unroll
        for (int p = 0; p < NLP; p++)
            #pragma unroll
            for (int o = 16; o > 0; o >>= 1) {
                u64 other = __shfl_xor_sync(0xffffffffu, acc[t][p], o);
                acc[t][p] = fadd2(acc[t][p], other);
            }

    // ---- bias + bias-softmax precompute (cheap, per thread) ----
    float bb[LL], be[LL];
    #pragma unroll
    for (int j = 0; j < LL; j++) bb[j] = bias[j];
    float bmx = bb[0];
    #pragma unroll
    for (int j = 1; j < LL; j++) bmx = fmaxf(bmx, bb[j]);
    float bsum = 0.f;
    #pragma unroll
    for (int j = 0; j < LL; j++) { be[j] = expf(bb[j] - bmx); bsum += be[j]; }
    float binv = 1.f / bsum;

    // ---- finalize: lanes 0..3 each own one token (static acc indexing) ----
    #pragma unroll
    for (int t = 0; t < TPW; t++) {
        if (lane == t) {
            int code = sh_slot[wid * TPW + t];
            if (code >= 0) {
                float v2[LL];
                float mx = -1e30f;
                #pragma unroll
                for (int p = 0; p < NLP; p++) {
                    float lo, hi;
                    unpack2(acc[t][p], lo, hi);
                    v2[2*p] = lo + bb[2*p];
                    mx = fmaxf(mx, v2[2*p]);
                    if (2*p + 1 < LL) {
                        v2[2*p+1] = hi + bb[2*p+1];
                        mx = fmaxf(mx, v2[2*p+1]);
                    }
                }
                float ssum = 0.f;
                #pragma unroll
                for (int j = 0; j < LL; j++) { v2[j] = expf(v2[j] - mx); ssum += v2[j]; }
                float inv = 1.f / ssum;
                float* o = out + ((size_t)row * SS + code) * LL;
                #pragma unroll
                for (int j = 0; j < LL; j++) o[j] = v2[j] * inv;
            } else {
                int islot = ~code;
                float* o = out + ((size_t)row * SS + islot) * LL;
                #pragma unroll
                for (int j = 0; j < LL; j++) o[j] = be[j] * binv;
            }
        }
    }
}

// ---------------------------------------------------------------------------
// Launch. Inputs (metadata order): sequence_output f32[64*512*768],
// valid_mask i32[64*512], W f32[768*9], b f32[9]. Output f32[64*512*9].
// ---------------------------------------------------------------------------
extern "C" void kernel_launch(void* const* d_in, const int* in_sizes, int n_in,
                              void* d_out, int out_size) {
    const float* X    = (const float*)d_in[0];
    const int*   mask = (const int*)d_in[1];
    const float* W    = (const float*)d_in[2];
    const float* bias = (const float*)d_in[3];
    float* out = (float*)d_out;

    bertner_kernel<<<NTOK / TOKPB, 256>>>(X, mask, W, bias, out);
}

// round 5
// speedup vs baseline: 1.0008x; 1.0008x over previous
#include <cuda_runtime.h>
#include <math.h>

#define BB 64
#define SS 512
#define HH 768
#define LL 9
#define NTOK (BB*SS)
#define TPW 4              // tokens per warp
#define WPB 8              // warps per block (256 threads)
#define TOKPB (TPW*WPB)    // 32 tokens per block (one row spans 16 blocks)

typedef unsigned long long u64;

__device__ __forceinline__ u64 pack2(float lo, float hi) {
    u64 r; asm("mov.b64 %0, {%1, %2};" : "=l"(r) : "f"(lo), "f"(hi)); return r;
}
__device__ __forceinline__ void unpack2(u64 v, float &lo, float &hi) {
    asm("mov.b64 {%0, %1}, %2;" : "=f"(lo), "=f"(hi) : "l"(v));
}
__device__ __forceinline__ void ffma2(u64 &d, u64 a, u64 b) {
    asm("fma.rn.f32x2 %0, %1, %2, %0;" : "+l"(d) : "l"(a), "l"(b));
}

// ---------------------------------------------------------------------------
// Single fused kernel:
//   1. per-block re-scan of this row's valid_mask -> slot code per token
//   2. tall-skinny GEMM [4 tok/warp, 768] @ [768, 9]:
//      - X via LDG.128 (lane owns k = 4*lane + 128*i, 6 iters)
//      - W transposed in smem (shWT[j][k]) -> LDS.128 gives two f32x2
//        k-pair operands per label; zero pack movs in the hot loop
//      - f32x2 FMAs accumulate k-pair partial sums
//   3. warp butterfly reduce + bias + softmax + compacting scatter
//      (invalid tokens write softmax(bias) to tail slots; bijection)
// ---------------------------------------------------------------------------
__global__ __launch_bounds__(256, 2) void bertner_kernel(
    const float* __restrict__ X, const int* __restrict__ mask,
    const float* __restrict__ W, const float* __restrict__ bias,
    float* __restrict__ out) {

    __shared__ float shWT[LL][HH];     // 27648 B, transposed W
    __shared__ int   sh_slot[TOKPB];
    __shared__ int   sh_wsum[WPB];

    int tid  = threadIdx.x;
    int lane = tid & 31;
    int wid  = tid >> 5;

    // ---- W transpose into smem: thread handles whole W rows (k), writes
    //      shWT[j][k] -> store banks = k mod 32, conflict-free per j step ----
    for (int k = tid; k < HH; k += 256) {
        #pragma unroll
        for (int j = 0; j < LL; j++) shWT[j][k] = W[k * LL + j];
    }

    // ---- per-row compaction scan (block redundantly scans its whole row) ----
    int tokblk = blockIdx.x * TOKPB;
    int row    = tokblk >> 9;          // / SS
    int r0     = tokblk & (SS - 1);    // row-local index of this block's first token

    int2 m2 = ((const int2*)(mask + row * SS))[tid];   // tokens 2*tid, 2*tid+1
    int msum = m2.x + m2.y;
    int v = msum;
    #pragma unroll
    for (int o = 1; o < 32; o <<= 1) {
        int n = __shfl_up_sync(0xffffffffu, v, o);
        if (lane >= o) v += n;
    }
    if (lane == 31) sh_wsum[wid] = v;
    __syncthreads();

    int wpre = 0, total = 0;
    #pragma unroll
    for (int w = 0; w < WPB; w++) {
        int s = sh_wsum[w];
        if (w < wid) wpre += s;
        total += s;
    }
    int run = wpre + v - msum;         // exclusive valid-prefix before token 2*tid

    int mm[2] = {m2.x, m2.y};
    #pragma unroll
    for (int c = 0; c < 2; c++) {
        int sc = 2 * tid + c;
        int code;
        if (mm[c]) { code = run; run++; }
        else       { code = ~(total + sc - run); }   // tail slot, encoded negative
        if (sc >= r0 && sc < r0 + TOKPB) sh_slot[sc - r0] = code;
    }
    __syncthreads();   // covers shWT + sh_slot

    // ---- main GEMM: warp handles 4 tokens; lane owns k = 4*lane + 128*i ----
    int tok0 = tokblk + wid * TPW;
    const float* xb = X + (size_t)tok0 * HH + 4 * lane;

    u64 acc[TPW][LL];
    #pragma unroll
    for (int t = 0; t < TPW; t++)
        #pragma unroll
        for (int j = 0; j < LL; j++) acc[t][j] = 0ull;

    #pragma unroll 2
    for (int i = 0; i < HH / 128; i++) {      // 6 iterations
        int k0 = i * 128;
        float4 xv[TPW];
        #pragma unroll
        for (int t = 0; t < TPW; t++)
            xv[t] = __ldcs((const float4*)(xb + t * HH + k0));

        u64 x01[TPW], x23[TPW];
        #pragma unroll
        for (int t = 0; t < TPW; t++) {
            x01[t] = pack2(xv[t].x, xv[t].y);
            x23[t] = pack2(xv[t].z, xv[t].w);
        }

        const float* wk = &shWT[0][k0 + 4 * lane];
        #pragma unroll
        for (int j = 0; j < LL; j++) {
            float4 wv = *(const float4*)(wk + j * HH);   // LDS.128, conflict-free
            u64 w01 = pack2(wv.x, wv.y);
            u64 w23 = pack2(wv.z, wv.w);
            #pragma unroll
            for (int t = 0; t < TPW; t++) {
                ffma2(acc[t][j], x01[t], w01);
                ffma2(acc[t][j], x23[t], w23);
            }
        }
    }

    // ---- fold k-pairs, then butterfly: every lane ends with full sums ----
    float r[TPW][LL];
    #pragma unroll
    for (int t = 0; t < TPW; t++)
        #pragma unroll
        for (int j = 0; j < LL; j++) {
            float lo, hi;
            unpack2(acc[t][j], lo, hi);
            r[t][j] = lo + hi;
        }
    #pragma unroll
    for (int t = 0; t < TPW; t++)
        #pragma unroll
        for (int j = 0; j < LL; j++)
            #pragma unroll
            for (int o = 16; o > 0; o >>= 1)
                r[t][j] += __shfl_xor_sync(0xffffffffu, r[t][j], o);

    // ---- bias + bias-softmax precompute (cheap, per thread) ----
    float bb[LL], be[LL];
    #pragma unroll
    for (int j = 0; j < LL; j++) bb[j] = bias[j];
    float bmx = bb[0];
    #pragma unroll
    for (int j = 1; j < LL; j++) bmx = fmaxf(bmx, bb[j]);
    float bsum = 0.f;
    #pragma unroll
    for (int j = 0; j < LL; j++) { be[j] = expf(bb[j] - bmx); bsum += be[j]; }
    float binv = 1.f / bsum;

    // ---- finalize: lanes 0..3 each own one token (static indexing) ----
    #pragma unroll
    for (int t = 0; t < TPW; t++) {
        if (lane == t) {
            int code = sh_slot[wid * TPW + t];
            if (code >= 0) {
                float v2[LL];
                float mx = -1e30f;
                #pragma unroll
                for (int j = 0; j < LL; j++) {
                    v2[j] = r[t][j] + bb[j];
                    mx = fmaxf(mx, v2[j]);
                }
                float ssum = 0.f;
                #pragma unroll
                for (int j = 0; j < LL; j++) { v2[j] = expf(v2[j] - mx); ssum += v2[j]; }
                float inv = 1.f / ssum;
                float* o = out + ((size_t)row * SS + code) * LL;
                #pragma unroll
                for (int j = 0; j < LL; j++) o[j] = v2[j] * inv;
            } else {
                int islot = ~code;
                float* o = out + ((size_t)row * SS + islot) * LL;
                #pragma unroll
                for (int j = 0; j < LL; j++) o[j] = be[j] * binv;
            }
        }
    }
}

// ---------------------------------------------------------------------------
// Launch. Inputs (metadata order): sequence_output f32[64*512*768],
// valid_mask i32[64*512], W f32[768*9], b f32[9]. Output f32[64*512*9].
// ---------------------------------------------------------------------------
extern "C" void kernel_launch(void* const* d_in, const int* in_sizes, int n_in,
                              void* d_out, int out_size) {
    const float* X    = (const float*)d_in[0];
    const int*   mask = (const int*)d_in[1];
    const float* W    = (const float*)d_in[2];
    const float* bias = (const float*)d_in[3];
    float* out = (float*)d_out;

    bertner_kernel<<<NTOK / TOKPB, 256>>>(X, mask, W, bias, out);
}